// round 2
// baseline (speedup 1.0000x reference)
#include <cuda_runtime.h>
#include <cstdint>

typedef unsigned long long ull;

__device__ __forceinline__ ull pack2(float a, float b) {
    ull r; asm("mov.b64 %0,{%1,%2};" : "=l"(r) : "f"(a), "f"(b)); return r;
}
__device__ __forceinline__ void fma2(ull& d, ull a, ull b) {
    asm("fma.rn.f32x2 %0,%1,%2,%3;" : "=l"(d) : "l"(a), "l"(b), "l"(d));
}
__device__ __forceinline__ float lo2(ull a) { return __uint_as_float((unsigned)a); }
__device__ __forceinline__ float hi2(ull a) { return __uint_as_float((unsigned)(a >> 32)); }

// Intermediate t4: [l][n][h][w][o]  (o fastest), 128*2*56*56*4 floats = 12.85 MB
__device__ float g_t4[128 * 2 * 56 * 56 * 4];

// ---------------------------------------------------------------------------
// Stage 1: t4[l,n,h,w,o] = sum_{k<64,i<3} xr[l,2k+n,h+i-1,w] * w1[k,i,o]
// xr = x rolled +1 along H (wrap), taps zero-padded outside [0,56).
// Block: (14 w-quads, 14 h-groups) per (n,l). Thread: 4h x 4w x 4o,
// f32x2 accumulators paired over (w0,w1)/(w2,w3).
// ---------------------------------------------------------------------------
__global__ __launch_bounds__(196) void stage1_kernel(
    const float* __restrict__ x, const float* __restrict__ w1)
{
    __shared__ __align__(16) ull w1p[768];   // [k][i][o] broadcast-packed (w,w)

    const int tid = threadIdx.y * 14 + threadIdx.x;
    for (int idx = tid; idx < 768; idx += 196) {
        float v = w1[idx];                   // w1 flat layout matches [k][i][o]
        w1p[idx] = pack2(v, v);
    }
    __syncthreads();

    const int n  = blockIdx.x;
    const int l  = blockIdx.y;
    const int w0 = threadIdx.x * 4;
    const int h0 = threadIdx.y * 4;

    // 6 virtual source rows h0-1 .. h0+4 : map through roll + zero pad
    int off[6];
#pragma unroll
    for (int r = 0; r < 6; r++) {
        int hv = h0 - 1 + r;
        if (hv < 0 || hv >= 56) off[r] = -1;
        else off[r] = ((hv == 0) ? 55 : hv - 1) * 56 + w0;
    }

    ull acc[4][4][2];                        // [hh][o][wpair]
#pragma unroll
    for (int hh = 0; hh < 4; hh++)
#pragma unroll
        for (int o = 0; o < 4; o++) { acc[hh][o][0] = 0ull; acc[hh][o][1] = 0ull; }

    const float* xb = x + ((size_t)l * 128 + n) * 3136;   // channel c = 2k+n

#pragma unroll 2
    for (int k = 0; k < 64; k++) {
        ulonglong2 v[6];
#pragma unroll
        for (int r = 0; r < 6; r++) {
            if (off[r] >= 0) v[r] = *reinterpret_cast<const ulonglong2*>(xb + off[r]);
            else { v[r].x = 0ull; v[r].y = 0ull; }
        }
        const ulonglong2* wk = reinterpret_cast<const ulonglong2*>(&w1p[k * 12]);
        ull wv[12];
#pragma unroll
        for (int p = 0; p < 6; p++) { ulonglong2 t = wk[p]; wv[2 * p] = t.x; wv[2 * p + 1] = t.y; }

#pragma unroll
        for (int i = 0; i < 3; i++)
#pragma unroll
            for (int o = 0; o < 4; o++) {
                ull wb = wv[i * 4 + o];
#pragma unroll
                for (int hh = 0; hh < 4; hh++) {
                    fma2(acc[hh][o][0], v[hh + i].x, wb);
                    fma2(acc[hh][o][1], v[hh + i].y, wb);
                }
            }
        xb += 2 * 3136;
    }

    // Store to t4 [l][n][h][w][o]: per hh, 16 contiguous floats -> 4x STG.128
    float* t4 = g_t4 + ((((size_t)l * 2 + n) * 56 + h0) * 56 + w0) * 4;
#pragma unroll
    for (int hh = 0; hh < 4; hh++) {
        float4* p = reinterpret_cast<float4*>(t4 + hh * 224);
        p[0] = make_float4(lo2(acc[hh][0][0]), lo2(acc[hh][1][0]), lo2(acc[hh][2][0]), lo2(acc[hh][3][0]));
        p[1] = make_float4(hi2(acc[hh][0][0]), hi2(acc[hh][1][0]), hi2(acc[hh][2][0]), hi2(acc[hh][3][0]));
        p[2] = make_float4(lo2(acc[hh][0][1]), lo2(acc[hh][1][1]), lo2(acc[hh][2][1]), lo2(acc[hh][3][1]));
        p[3] = make_float4(hi2(acc[hh][0][1]), hi2(acc[hh][1][1]), hi2(acc[hh][2][1]), hi2(acc[hh][3][1]));
    }
}

// ---------------------------------------------------------------------------
// Stage 2: out[l, 4j+o, h, w] = sum_{i<2,kk<3} t4[l,i,h,w+kk-1,o] * w2[i,kk,j]
// One block per (l,h). t4 rows staged in smem twice (normal + shifted) so all
// w-tap pairs are aligned LDS.64. Thread: (w-quad tx, ty = o*8+jgroup), 4 j.
// ---------------------------------------------------------------------------
__global__ __launch_bounds__(448) void stage2_kernel(
    const float* __restrict__ w2, float* __restrict__ out)
{
    __shared__ __align__(16) float bufM[8][56];   // [i*4+o][w]   = row[w]
    __shared__ __align__(16) float bufS[8][60];   // [c][x]       = row[x-1], 0 at x=0,57
    __shared__ __align__(16) ull   w2p[192];      // [i][kk][j] broadcast-packed

    const int h = blockIdx.x;
    const int l = blockIdx.y;
    const int tx = threadIdx.x, ty = threadIdx.y;
    const int tid = ty * 14 + tx;

    {   // fill t4 rows: 448 elements, one per thread
        int w = tid >> 3, i = (tid >> 2) & 1, o = tid & 3;
        int c = i * 4 + o;
        float v = g_t4[((size_t)l * 112 + h) * 224 + (size_t)i * 56 * 224 + w * 4 + o];
        bufM[c][w] = v;
        bufS[c][w + 1] = v;
    }
    if (tid < 16) { int c = tid >> 1; bufS[c][(tid & 1) ? 57 : 0] = 0.f; }
    for (int idx = tid; idx < 192; idx += 448) {  // w2 flat layout matches [i][kk][j]
        float v = w2[idx];
        w2p[idx] = pack2(v, v);
    }
    __syncthreads();

    const int o  = ty >> 3;
    const int j0 = (ty & 7) * 4;
    const int w0 = tx * 4;

    ull W[2][3][4];
#pragma unroll
    for (int i = 0; i < 2; i++)
#pragma unroll
        for (int kk = 0; kk < 3; kk++)
#pragma unroll
            for (int jj = 0; jj < 4; jj++)
                W[i][kk][jj] = w2p[i * 96 + kk * 32 + j0 + jj];

    ull acc[4][2];
#pragma unroll
    for (int jj = 0; jj < 4; jj++) { acc[jj][0] = 0ull; acc[jj][1] = 0ull; }

#pragma unroll
    for (int i = 0; i < 2; i++) {
        const int c = i * 4 + o;
#pragma unroll
        for (int kk = 0; kk < 3; kk++) {
            ull p0, p1;
            if (kk == 1) {            // taps (w), (w+1): aligned in bufM
                p0 = *reinterpret_cast<const ull*>(&bufM[c][w0]);
                p1 = *reinterpret_cast<const ull*>(&bufM[c][w0 + 2]);
            } else if (kk == 0) {     // taps (w-1): bufS[x]=row[x-1]
                p0 = *reinterpret_cast<const ull*>(&bufS[c][w0]);
                p1 = *reinterpret_cast<const ull*>(&bufS[c][w0 + 2]);
            } else {                  // taps (w+1) pairs starting at row[w0+1]
                p0 = *reinterpret_cast<const ull*>(&bufS[c][w0 + 2]);
                p1 = *reinterpret_cast<const ull*>(&bufS[c][w0 + 4]);
            }
#pragma unroll
            for (int jj = 0; jj < 4; jj++) {
                fma2(acc[jj][0], p0, W[i][kk][jj]);
                fma2(acc[jj][1], p1, W[i][kk][jj]);
            }
        }
    }

#pragma unroll
    for (int jj = 0; jj < 4; jj++) {
        int cc = (j0 + jj) * 4 + o;
        float4* p = reinterpret_cast<float4*>(out + ((size_t)l * 128 + cc) * 3136 + h * 56 + w0);
        *p = make_float4(lo2(acc[jj][0]), hi2(acc[jj][0]), lo2(acc[jj][1]), hi2(acc[jj][1]));
    }
}

extern "C" void kernel_launch(void* const* d_in, const int* in_sizes, int n_in,
                              void* d_out, int out_size)
{
    const float* x  = (const float*)d_in[0];
    const float* w1 = (const float*)d_in[1];
    const float* w2 = (const float*)d_in[2];
    float* out = (float*)d_out;

    stage1_kernel<<<dim3(2, 128), dim3(14, 14)>>>(x, w1);
    stage2_kernel<<<dim3(56, 128), dim3(14, 32)>>>(w2, out);
}

// round 3
// speedup vs baseline: 1.3685x; 1.3685x over previous
#include <cuda_runtime.h>
#include <cstdint>

typedef unsigned long long ull;

__device__ __forceinline__ ull pack2(float a, float b) {
    ull r; asm("mov.b64 %0,{%1,%2};" : "=l"(r) : "f"(a), "f"(b)); return r;
}
__device__ __forceinline__ void fma2(ull& d, ull a, ull b) {
    asm("fma.rn.f32x2 %0,%1,%2,%3;" : "=l"(d) : "l"(a), "l"(b), "l"(d));
}
__device__ __forceinline__ float lo2(ull a) { return __uint_as_float((unsigned)a); }
__device__ __forceinline__ float hi2(ull a) { return __uint_as_float((unsigned)(a >> 32)); }

#define CH 8   // h rows per block (56 = 7 * 8)

// Fused kernel:
//   Phase 1: t4[n,h,w,o] = sum_{k<64,i<3} xr[l,2k+n,h+i-1,w] * w1[k,i,o]  -> smem
//   Phase 2: out[l,4j+o,h,w] = sum_{i<2,kk<3} t4[i,h,w+kk-1,o] * w2[i,kk,j]
// t4 never touches DRAM. Two smem copies of t4 (normal + shifted by one float)
// make every w-tap pair an aligned 8-byte LDS for f32x2 math.
__global__ __launch_bounds__(448, 2) void fused_kernel(
    const float* __restrict__ x, const float* __restrict__ w1,
    const float* __restrict__ w2, float* __restrict__ out)
{
    __shared__ __align__(16) ull   w1p[768];          // [k][i][o] packed (w,w)
    __shared__ __align__(16) ull   w2p[192];          // [i][kk][j] packed (w,w)
    __shared__ __align__(16) float M[2][CH][4][56];   // [n][h][o][w]   = t4 row
    __shared__ __align__(16) float S[2][CH][4][60];   // [n][h][o][x]   = t4[x-1], 0 pad

    const int tid = threadIdx.x;
    const int h0  = blockIdx.x * CH;
    const int l   = blockIdx.y;

    for (int idx = tid; idx < 768; idx += 448) { float v = w1[idx]; w1p[idx] = pack2(v, v); }
    if (tid < 192) { float v = w2[tid]; w2p[tid] = pack2(v, v); }
    if (tid < 128) {   // zero the pad cells of S: x = 0 and x = 57
        int n = tid >> 6, rem = tid & 63, h = rem >> 3, o = (rem >> 1) & 3;
        S[n][h][o][(tid & 1) ? 57 : 0] = 0.f;
    }
    __syncthreads();

    // ---------------- Phase 1 ----------------
    {
        const int wp = tid % 28;            // w-pair index
        const int h  = (tid / 28) % CH;
        const int n  = tid / 224;
        const int w0 = wp * 2;
        const int ho = h0 + h;

        int off[3];                         // virtual rows ho-1..ho+1 through roll+pad
#pragma unroll
        for (int i = 0; i < 3; i++) {
            int hv = ho - 1 + i;
            off[i] = (hv < 0 || hv >= 56) ? -1 : ((hv == 0 ? 55 : hv - 1) * 56 + w0);
        }

        ull acc[4] = {0ull, 0ull, 0ull, 0ull};
        const float* xb = x + ((size_t)l * 128 + n) * 3136;   // channel c = 2k+n

#pragma unroll 2
        for (int k = 0; k < 64; k++) {
            ull v[3];
#pragma unroll
            for (int i = 0; i < 3; i++)
                v[i] = (off[i] >= 0) ? *reinterpret_cast<const ull*>(xb + off[i]) : 0ull;

            const ulonglong2* wk = reinterpret_cast<const ulonglong2*>(&w1p[k * 12]);
            ull wv[12];
#pragma unroll
            for (int p = 0; p < 6; p++) { ulonglong2 t = wk[p]; wv[2 * p] = t.x; wv[2 * p + 1] = t.y; }

#pragma unroll
            for (int i = 0; i < 3; i++)
#pragma unroll
                for (int o = 0; o < 4; o++)
                    fma2(acc[o], v[i], wv[i * 4 + o]);

            xb += 2 * 3136;
        }

#pragma unroll
        for (int o = 0; o < 4; o++) {
            *reinterpret_cast<ull*>(&M[n][h][o][w0]) = acc[o];   // w0 even -> aligned
            S[n][h][o][w0 + 1] = lo2(acc[o]);
            S[n][h][o][w0 + 2] = hi2(acc[o]);
        }
    }
    __syncthreads();

    // ---------------- Phase 2 ----------------
    {
        const int tx = tid % 14;
        const int ty = tid / 14;
        const int o  = ty >> 3;
        const int j0 = (ty & 7) * 4;
        const int w0 = tx * 4;

        for (int h = 0; h < CH; h++) {
            ull acc[4][2];
#pragma unroll
            for (int jj = 0; jj < 4; jj++) { acc[jj][0] = 0ull; acc[jj][1] = 0ull; }

#pragma unroll
            for (int i = 0; i < 2; i++) {
#pragma unroll
                for (int kk = 0; kk < 3; kk++) {
                    ull p0, p1;
                    if (kk == 1) {
                        p0 = *reinterpret_cast<const ull*>(&M[i][h][o][w0]);
                        p1 = *reinterpret_cast<const ull*>(&M[i][h][o][w0 + 2]);
                    } else if (kk == 0) {
                        p0 = *reinterpret_cast<const ull*>(&S[i][h][o][w0]);
                        p1 = *reinterpret_cast<const ull*>(&S[i][h][o][w0 + 2]);
                    } else {
                        p0 = *reinterpret_cast<const ull*>(&S[i][h][o][w0 + 2]);
                        p1 = *reinterpret_cast<const ull*>(&S[i][h][o][w0 + 4]);
                    }
                    ulonglong2 Wa = *reinterpret_cast<const ulonglong2*>(&w2p[i * 96 + kk * 32 + j0]);
                    ulonglong2 Wb = *reinterpret_cast<const ulonglong2*>(&w2p[i * 96 + kk * 32 + j0 + 2]);
                    fma2(acc[0][0], p0, Wa.x); fma2(acc[0][1], p1, Wa.x);
                    fma2(acc[1][0], p0, Wa.y); fma2(acc[1][1], p1, Wa.y);
                    fma2(acc[2][0], p0, Wb.x); fma2(acc[2][1], p1, Wb.x);
                    fma2(acc[3][0], p0, Wb.y); fma2(acc[3][1], p1, Wb.y);
                }
            }

#pragma unroll
            for (int jj = 0; jj < 4; jj++) {
                int cc = (j0 + jj) * 4 + o;
                float4* p = reinterpret_cast<float4*>(
                    out + ((size_t)l * 128 + cc) * 3136 + (h0 + h) * 56 + w0);
                *p = make_float4(lo2(acc[jj][0]), hi2(acc[jj][0]),
                                 lo2(acc[jj][1]), hi2(acc[jj][1]));
            }
        }
    }
}

extern "C" void kernel_launch(void* const* d_in, const int* in_sizes, int n_in,
                              void* d_out, int out_size)
{
    const float* x  = (const float*)d_in[0];
    const float* w1 = (const float*)d_in[1];
    const float* w2 = (const float*)d_in[2];
    float* out = (float*)d_out;

    fused_kernel<<<dim3(7, 128), 448>>>(x, w1, w2, out);
}

// round 4
// speedup vs baseline: 1.4281x; 1.0435x over previous
#include <cuda_runtime.h>
#include <cstdint>

typedef unsigned long long ull;

__device__ __forceinline__ ull pack2(float a, float b) {
    ull r; asm("mov.b64 %0,{%1,%2};" : "=l"(r) : "f"(a), "f"(b)); return r;
}
__device__ __forceinline__ void fma2(ull& d, ull a, ull b) {
    asm("fma.rn.f32x2 %0,%1,%2,%3;" : "=l"(d) : "l"(a), "l"(b), "l"(d));
}
__device__ __forceinline__ void add2(ull& d, ull a) {
    asm("add.rn.f32x2 %0,%1,%2;" : "=l"(d) : "l"(d), "l"(a));
}
__device__ __forceinline__ float lo2(ull a) { return __uint_as_float((unsigned)a); }
__device__ __forceinline__ float hi2(ull a) { return __uint_as_float((unsigned)(a >> 32)); }

#define CH 8   // h rows per block (56 = 7 * 8)

// Fused, k-split kernel:
//   Phase 1: t4[n,h,w,o] = sum_{k<64,i<3} xr[l,2k+n,h+i-1,w] * w1[k,i,o]  -> smem
//            (448 thr = 2 k-halves x (n,h,w-quad); smem reduction joins halves)
//   Phase 2: out[l,4j+o,h,w] = sum_{i<2,kk<3} t4[i,h,w+kk-1,o] * w2[i,kk,j]
__global__ __launch_bounds__(448, 2) void fused_kernel(
    const float* __restrict__ x, const float* __restrict__ w1,
    const float* __restrict__ w2, float* __restrict__ out)
{
    __shared__ __align__(16) ull   w1p[768];          // [k][i][o] packed (w,w)
    __shared__ __align__(16) ull   w2p[192];          // [i][kk][j] packed (w,w)
    __shared__ __align__(16) float M[2][CH][4][56];   // [n][h][o][w]  = t4 row
    __shared__ __align__(16) float S[2][CH][4][60];   // [n][h][o][x]  = t4[x-1], 0 pad
    __shared__ __align__(16) ull   pbuf[224 * 8];     // k-half-1 partial accumulators

    const int tid = threadIdx.x;
    const int h0  = blockIdx.x * CH;
    const int l   = blockIdx.y;

    for (int idx = tid; idx < 768; idx += 448) { float v = w1[idx]; w1p[idx] = pack2(v, v); }
    if (tid < 192) { float v = w2[tid]; w2p[tid] = pack2(v, v); }
    if (tid < 128) {   // zero the pad cells of S: x = 0 and x = 57
        int n = tid >> 6, rem = tid & 63, h = rem >> 3, o = (rem >> 1) & 3;
        S[n][h][o][(tid & 1) ? 57 : 0] = 0.f;
    }
    __syncthreads();

    // ---------------- Phase 1 ----------------
    {
        const int wq = tid % 14;            // w-quad index
        const int h  = (tid / 14) % CH;
        const int n  = (tid / 112) % 2;
        const int kh = tid / 224;           // k-half
        const int w0 = wq * 4;
        const int ho = h0 + h;
        const int item = (n * CH + h) * 14 + wq;

        int off[3];                         // virtual rows ho-1..ho+1 through roll+pad
#pragma unroll
        for (int i = 0; i < 3; i++) {
            int hv = ho - 1 + i;
            off[i] = (hv < 0 || hv >= 56) ? -1 : ((hv == 0 ? 55 : hv - 1) * 56 + w0);
        }

        ull acc[4][2];
#pragma unroll
        for (int o = 0; o < 4; o++) { acc[o][0] = 0ull; acc[o][1] = 0ull; }

        // channel c = 2*(kh*32 + kk) + n
        const float* xb = x + ((size_t)l * 128 + (size_t)kh * 64 + n) * 3136;

        ulonglong2 v[3];                    // current k's 3 tap rows (depth-1 pipeline)
#pragma unroll
        for (int i = 0; i < 3; i++) {
            if (off[i] >= 0) v[i] = *reinterpret_cast<const ulonglong2*>(xb + off[i]);
            else { v[i].x = 0ull; v[i].y = 0ull; }
        }

#pragma unroll 2
        for (int kk = 0; kk < 32; kk++) {
            // prefetch next k's taps before consuming current
            ulonglong2 vn[3];
            if (kk < 31) {
                const float* xn = xb + 2 * 3136;
#pragma unroll
                for (int i = 0; i < 3; i++) {
                    if (off[i] >= 0) vn[i] = *reinterpret_cast<const ulonglong2*>(xn + off[i]);
                    else { vn[i].x = 0ull; vn[i].y = 0ull; }
                }
            }

            const ulonglong2* wk = reinterpret_cast<const ulonglong2*>(&w1p[(kh * 32 + kk) * 12]);
            ull wv[12];
#pragma unroll
            for (int p = 0; p < 6; p++) { ulonglong2 t = wk[p]; wv[2 * p] = t.x; wv[2 * p + 1] = t.y; }

#pragma unroll
            for (int i = 0; i < 3; i++)
#pragma unroll
                for (int o = 0; o < 4; o++) {
                    fma2(acc[o][0], v[i].x, wv[i * 4 + o]);
                    fma2(acc[o][1], v[i].y, wv[i * 4 + o]);
                }

            if (kk < 31) {
#pragma unroll
                for (int i = 0; i < 3; i++) v[i] = vn[i];
                xb += 2 * 3136;
            }
        }

        if (kh == 1) {                      // publish partials
            ulonglong2* p = reinterpret_cast<ulonglong2*>(&pbuf[item * 8]);
#pragma unroll
            for (int o = 0; o < 4; o++) { ulonglong2 t; t.x = acc[o][0]; t.y = acc[o][1]; p[o] = t; }
        }
        __syncthreads();
        if (kh == 0) {                      // join halves, write t4 rows
            const ulonglong2* p = reinterpret_cast<const ulonglong2*>(&pbuf[item * 8]);
#pragma unroll
            for (int o = 0; o < 4; o++) {
                ulonglong2 t = p[o];
                add2(acc[o][0], t.x);
                add2(acc[o][1], t.y);
                *reinterpret_cast<ull*>(&M[n][h][o][w0])     = acc[o][0];
                *reinterpret_cast<ull*>(&M[n][h][o][w0 + 2]) = acc[o][1];
                S[n][h][o][w0 + 1] = lo2(acc[o][0]);
                *reinterpret_cast<ull*>(&S[n][h][o][w0 + 2]) = pack2(hi2(acc[o][0]), lo2(acc[o][1]));
                S[n][h][o][w0 + 4] = hi2(acc[o][1]);
            }
        }
    }
    __syncthreads();

    // ---------------- Phase 2 ----------------
    {
        const int tx = tid % 14;
        const int ty = tid / 14;
        const int o  = ty >> 3;
        const int j0 = (ty & 7) * 4;
        const int w0 = tx * 4;

        for (int h = 0; h < CH; h++) {
            ull acc[4][2];
#pragma unroll
            for (int jj = 0; jj < 4; jj++) { acc[jj][0] = 0ull; acc[jj][1] = 0ull; }

#pragma unroll
            for (int i = 0; i < 2; i++) {
#pragma unroll
                for (int kk = 0; kk < 3; kk++) {
                    ull p0, p1;
                    if (kk == 1) {
                        p0 = *reinterpret_cast<const ull*>(&M[i][h][o][w0]);
                        p1 = *reinterpret_cast<const ull*>(&M[i][h][o][w0 + 2]);
                    } else if (kk == 0) {
                        p0 = *reinterpret_cast<const ull*>(&S[i][h][o][w0]);
                        p1 = *reinterpret_cast<const ull*>(&S[i][h][o][w0 + 2]);
                    } else {
                        p0 = *reinterpret_cast<const ull*>(&S[i][h][o][w0 + 2]);
                        p1 = *reinterpret_cast<const ull*>(&S[i][h][o][w0 + 4]);
                    }
                    ulonglong2 Wa = *reinterpret_cast<const ulonglong2*>(&w2p[i * 96 + kk * 32 + j0]);
                    ulonglong2 Wb = *reinterpret_cast<const ulonglong2*>(&w2p[i * 96 + kk * 32 + j0 + 2]);
                    fma2(acc[0][0], p0, Wa.x); fma2(acc[0][1], p1, Wa.x);
                    fma2(acc[1][0], p0, Wa.y); fma2(acc[1][1], p1, Wa.y);
                    fma2(acc[2][0], p0, Wb.x); fma2(acc[2][1], p1, Wb.x);
                    fma2(acc[3][0], p0, Wb.y); fma2(acc[3][1], p1, Wb.y);
                }
            }

#pragma unroll
            for (int jj = 0; jj < 4; jj++) {
                int cc = (j0 + jj) * 4 + o;
                float4* p = reinterpret_cast<float4*>(
                    out + ((size_t)l * 128 + cc) * 3136 + (h0 + h) * 56 + w0);
                *p = make_float4(lo2(acc[jj][0]), hi2(acc[jj][0]),
                                 lo2(acc[jj][1]), hi2(acc[jj][1]));
            }
        }
    }
}

extern "C" void kernel_launch(void* const* d_in, const int* in_sizes, int n_in,
                              void* d_out, int out_size)
{
    const float* x  = (const float*)d_in[0];
    const float* w1 = (const float*)d_in[1];
    const float* w2 = (const float*)d_in[2];
    float* out = (float*)d_out;

    fused_kernel<<<dim3(7, 128), 448>>>(x, w1, w2, out);
}

// round 5
// speedup vs baseline: 1.4547x; 1.0186x over previous
#include <cuda_runtime.h>
#include <cstdint>

typedef unsigned long long ull;

__device__ __forceinline__ ull pack2(float a, float b) {
    ull r; asm("mov.b64 %0,{%1,%2};" : "=l"(r) : "f"(a), "f"(b)); return r;
}
__device__ __forceinline__ void fma2(ull& d, ull a, ull b) {
    asm("fma.rn.f32x2 %0,%1,%2,%3;" : "=l"(d) : "l"(a), "l"(b), "l"(d));
}
__device__ __forceinline__ void add2(ull& d, ull a) {
    asm("add.rn.f32x2 %0,%1,%2;" : "=l"(d) : "l"(d), "l"(a));
}
__device__ __forceinline__ float lo2(ull a) { return __uint_as_float((unsigned)a); }
__device__ __forceinline__ float hi2(ull a) { return __uint_as_float((unsigned)(a >> 32)); }

#define CH 8   // h rows per block (56 = 7 * 8)

__device__ __align__(16) float g_zero[32];   // never written: reads give 0

struct Smem {
    ull   w1p[768];              // [k][i][o] packed (w,w)
    ull   w2p[192];              // [i][kk][j] packed (w,w)
    float M[2][CH][4][56];       // [n][h][o][w]  = t4 row
    float S[2][CH][4][60];       // [n][h][o][x]  = t4[x-1], 0 pad
    ull   pbuf[4][112][17];      // [kq][item][(h*4+o)*2+wp], padded stride 17
};
#define SMEM_BYTES sizeof(Smem)

// Fused kernel. Phase 1: h-pair mapping (each thread loads 4 tap rows for 2
// output rows -> 2x tap redundancy instead of 3x), k-split 4 with fully
// parallel smem reduction. Phase 2: w-tap conv from smem t4 (M + shifted S).
__global__ __launch_bounds__(448, 2) void fused_kernel(
    const float* __restrict__ x, const float* __restrict__ w1,
    const float* __restrict__ w2, float* __restrict__ out)
{
    extern __shared__ __align__(16) char smraw[];
    Smem& sm = *reinterpret_cast<Smem*>(smraw);

    const int tid = threadIdx.x;
    const int h0  = blockIdx.x * CH;
    const int l   = blockIdx.y;

    for (int idx = tid; idx < 768; idx += 448) { float v = w1[idx]; sm.w1p[idx] = pack2(v, v); }
    if (tid < 192) { float v = w2[tid]; sm.w2p[tid] = pack2(v, v); }
    if (tid < 128) {   // zero the pad cells of S: x = 0 and x = 57
        int n = tid >> 6, rem = tid & 63, h = rem >> 3, o = (rem >> 1) & 3;
        sm.S[n][h][o][(tid & 1) ? 57 : 0] = 0.f;
    }
    __syncthreads();

    // ---------------- Phase 1 ----------------
    {
        const int kq  = tid / 112;          // k-quarter: k = kq*16 + kk
        const int rem = tid % 112;
        const int n   = rem / 56;
        const int hp  = (rem / 14) % 4;     // h-pair within chunk
        const int wq  = rem % 14;
        const int w0  = wq * 4;
        const int ha  = h0 + hp * 2;

        // 4 virtual tap rows ha-1 .. ha+2 through roll(+1) + zero pad
        const float* xb = x + ((size_t)l * 128 + (size_t)kq * 32 + n) * 3136;
        const float* rp[4]; int st[4];
#pragma unroll
        for (int r = 0; r < 4; r++) {
            int hv = ha - 1 + r;
            if (hv < 0 || hv >= 56) { rp[r] = g_zero; st[r] = 0; }
            else { rp[r] = xb + ((hv == 0 ? 55 : hv - 1) * 56 + w0); st[r] = 2 * 3136; }
        }

        ull acc[2][4][2];
#pragma unroll
        for (int h = 0; h < 2; h++)
#pragma unroll
            for (int o = 0; o < 4; o++) { acc[h][o][0] = 0ull; acc[h][o][1] = 0ull; }

        const ulonglong2* wbase = reinterpret_cast<const ulonglong2*>(&sm.w1p[kq * 192]);

#pragma unroll 2
        for (int kk = 0; kk < 16; kk++) {
            ulonglong2 v[4];
#pragma unroll
            for (int r = 0; r < 4; r++) {
                v[r] = *reinterpret_cast<const ulonglong2*>(rp[r]);
                rp[r] += st[r];
            }
#pragma unroll
            for (int p = 0; p < 6; p++) {
                ulonglong2 wv = wbase[kk * 6 + p];
                const int e0 = 2 * p,      i0 = e0 >> 2, o0 = e0 & 3;
                const int e1 = 2 * p + 1,  i1 = e1 >> 2, o1 = e1 & 3;
                fma2(acc[0][o0][0], v[i0].x,     wv.x);
                fma2(acc[0][o0][1], v[i0].y,     wv.x);
                fma2(acc[1][o0][0], v[i0 + 1].x, wv.x);
                fma2(acc[1][o0][1], v[i0 + 1].y, wv.x);
                fma2(acc[0][o1][0], v[i1].x,     wv.y);
                fma2(acc[0][o1][1], v[i1].y,     wv.y);
                fma2(acc[1][o1][0], v[i1 + 1].x, wv.y);
                fma2(acc[1][o1][1], v[i1 + 1].y, wv.y);
            }
        }

        // publish all quarters' partials
        {
            ull* dst = &sm.pbuf[kq][rem][0];
#pragma unroll
            for (int h = 0; h < 2; h++)
#pragma unroll
                for (int o = 0; o < 4; o++)
#pragma unroll
                    for (int wp = 0; wp < 2; wp++)
                        dst[(h * 4 + o) * 2 + wp] = acc[h][o][wp];
        }
    }
    __syncthreads();

    // parallel reduction + t4 smem write: thread = (item, o)
    {
        const int it = tid % 112;
        const int o2 = tid / 112;
        ull s[2][2];
#pragma unroll
        for (int h = 0; h < 2; h++)
#pragma unroll
            for (int wp = 0; wp < 2; wp++)
                s[h][wp] = sm.pbuf[0][it][(h * 4 + o2) * 2 + wp];
#pragma unroll
        for (int q = 1; q < 4; q++)
#pragma unroll
            for (int h = 0; h < 2; h++)
#pragma unroll
                for (int wp = 0; wp < 2; wp++)
                    add2(s[h][wp], sm.pbuf[q][it][(h * 4 + o2) * 2 + wp]);

        const int n  = it / 56;
        const int hp = (it / 14) % 4;
        const int wq = it % 14;
        const int w0 = wq * 4;
#pragma unroll
        for (int h = 0; h < 2; h++) {
            const int hr = hp * 2 + h;
            *reinterpret_cast<ull*>(&sm.M[n][hr][o2][w0])     = s[h][0];
            *reinterpret_cast<ull*>(&sm.M[n][hr][o2][w0 + 2]) = s[h][1];
            sm.S[n][hr][o2][w0 + 1] = lo2(s[h][0]);
            *reinterpret_cast<ull*>(&sm.S[n][hr][o2][w0 + 2]) = pack2(hi2(s[h][0]), lo2(s[h][1]));
            sm.S[n][hr][o2][w0 + 4] = hi2(s[h][1]);
        }
    }
    __syncthreads();

    // ---------------- Phase 2 ----------------
    {
        const int tx = tid % 14;
        const int ty = tid / 14;
        const int o  = ty >> 3;
        const int j0 = (ty & 7) * 4;
        const int w0 = tx * 4;

        for (int h = 0; h < CH; h++) {
            ull acc[4][2];
#pragma unroll
            for (int jj = 0; jj < 4; jj++) { acc[jj][0] = 0ull; acc[jj][1] = 0ull; }

#pragma unroll
            for (int i = 0; i < 2; i++) {
#pragma unroll
                for (int kk = 0; kk < 3; kk++) {
                    ull p0, p1;
                    if (kk == 1) {
                        p0 = *reinterpret_cast<const ull*>(&sm.M[i][h][o][w0]);
                        p1 = *reinterpret_cast<const ull*>(&sm.M[i][h][o][w0 + 2]);
                    } else if (kk == 0) {
                        p0 = *reinterpret_cast<const ull*>(&sm.S[i][h][o][w0]);
                        p1 = *reinterpret_cast<const ull*>(&sm.S[i][h][o][w0 + 2]);
                    } else {
                        p0 = *reinterpret_cast<const ull*>(&sm.S[i][h][o][w0 + 2]);
                        p1 = *reinterpret_cast<const ull*>(&sm.S[i][h][o][w0 + 4]);
                    }
                    ulonglong2 Wa = *reinterpret_cast<const ulonglong2*>(&sm.w2p[i * 96 + kk * 32 + j0]);
                    ulonglong2 Wb = *reinterpret_cast<const ulonglong2*>(&sm.w2p[i * 96 + kk * 32 + j0 + 2]);
                    fma2(acc[0][0], p0, Wa.x); fma2(acc[0][1], p1, Wa.x);
                    fma2(acc[1][0], p0, Wa.y); fma2(acc[1][1], p1, Wa.y);
                    fma2(acc[2][0], p0, Wb.x); fma2(acc[2][1], p1, Wb.x);
                    fma2(acc[3][0], p0, Wb.y); fma2(acc[3][1], p1, Wb.y);
                }
            }

#pragma unroll
            for (int jj = 0; jj < 4; jj++) {
                int cc = (j0 + jj) * 4 + o;
                float4* p = reinterpret_cast<float4*>(
                    out + ((size_t)l * 128 + cc) * 3136 + (h0 + h) * 56 + w0);
                *p = make_float4(lo2(acc[jj][0]), hi2(acc[jj][0]),
                                 lo2(acc[jj][1]), hi2(acc[jj][1]));
            }
        }
    }
}

extern "C" void kernel_launch(void* const* d_in, const int* in_sizes, int n_in,
                              void* d_out, int out_size)
{
    const float* x  = (const float*)d_in[0];
    const float* w1 = (const float*)d_in[1];
    const float* w2 = (const float*)d_in[2];
    float* out = (float*)d_out;

    cudaFuncSetAttribute(fused_kernel, cudaFuncAttributeMaxDynamicSharedMemorySize,
                         (int)SMEM_BYTES);
    fused_kernel<<<dim3(7, 128), 448, SMEM_BYTES>>>(x, w1, w2, out);
}

// round 6
// speedup vs baseline: 1.5692x; 1.0787x over previous
#include <cuda_runtime.h>
#include <cstdint>

typedef unsigned long long ull;

__device__ __forceinline__ ull pack2(float a, float b) {
    ull r; asm("mov.b64 %0,{%1,%2};" : "=l"(r) : "f"(a), "f"(b)); return r;
}
__device__ __forceinline__ void fma2(ull& d, ull a, ull b) {
    asm("fma.rn.f32x2 %0,%1,%2,%3;" : "=l"(d) : "l"(a), "l"(b), "l"(d));
}
__device__ __forceinline__ void add2(ull& d, ull a) {
    asm("add.rn.f32x2 %0,%1,%2;" : "=l"(d) : "l"(d), "l"(a));
}
__device__ __forceinline__ float lo2(ull a) { return __uint_as_float((unsigned)a); }
__device__ __forceinline__ float hi2(ull a) { return __uint_as_float((unsigned)(a >> 32)); }

#define CH 8                    // h rows per block (56 = 7 * 8)
#define NQUAD 1120              // 16B quads per tile: 4kq * 2n * 10rows * 14
#define XT_BYTES 19200          // bytes per x-tile buffer: 4*2*10*60*4

struct Smem {
    union {
        float xtile[2][4][2][10][60];   // [buf][kq][n][slot][w(pad 60)]
        ull   pbuf[4][112][17];         // partials, alias (xtile dead by then)
    } u;
    float M[2][CH][4][56];       // [n][h][o][w]  = t4 row
    float S[2][CH][4][60];       // [n][h][o][x]  = t4[x-1], 0 pad
    ull   w1p[768];              // [k][i][o] packed (w,w)
    ull   w2p[192];              // [i][kk][j] packed (w,w)
};
#define SMEM_BYTES sizeof(Smem)

// Fused kernel with cp.async double-buffered k-tile pipeline for phase 1.
// Tile t holds k = kq*16 + t for all 4 k-quarters (channels 32kq+2t+{0,1}),
// 10 tap rows each, staged coalesced into smem; compute reads padded smem.
__global__ __launch_bounds__(448, 2) void fused_kernel(
    const float* __restrict__ x, const float* __restrict__ w1,
    const float* __restrict__ w2, float* __restrict__ out)
{
    extern __shared__ __align__(16) char smraw[];
    Smem& sm = *reinterpret_cast<Smem*>(smraw);

    const int tid = threadIdx.x;
    const int h0  = blockIdx.x * CH;
    const int l   = blockIdx.y;

    // ---- per-thread cp.async quad descriptors (3 quads, last partial) ----
    const float* qsrc[3]; unsigned qdst[3]; int qsz[3];
#pragma unroll
    for (int i = 0; i < 3; i++) {
        int q  = tid + i * 448;          // i<2 always < NQUAD; i==2 iff tid<224
        int qq = (q < NQUAD) ? q : 0;
        int kq = qq / 280, n = (qq / 140) % 2, s = (qq / 14) % 10, wq = qq % 14;
        int hv  = h0 - 1 + s;            // virtual (rolled) tap row
        int inr = (hv >= 0 && hv < 56);
        int row = (hv == 0) ? 55 : hv - 1;
        qsrc[i] = x + ((size_t)l * 128 + 32 * kq + n) * 3136 + (inr ? row * 56 : 0) + wq * 4;
        qdst[i] = (unsigned)__cvta_generic_to_shared(&sm.u.xtile[0][kq][n][s][wq * 4]);
        qsz[i]  = inr ? 16 : 0;
    }

    auto issue = [&](int t) {
        unsigned bofs = (unsigned)((t & 1) * XT_BYTES);
        size_t   cofs = (size_t)(2 * t) * 3136;      // +2 channels per tile
#pragma unroll
        for (int i = 0; i < 3; i++) {
            if (i == 2 && tid >= 224) break;
            asm volatile("cp.async.cg.shared.global [%0], [%1], 16, %2;"
                         :: "r"(qdst[i] + bofs), "l"(qsrc[i] + cofs), "r"(qsz[i])
                         : "memory");
        }
        asm volatile("cp.async.commit_group;" ::: "memory");
    };

    issue(0); issue(1);                  // prologue: get DRAM going first

    for (int idx = tid; idx < 768; idx += 448) { float v = w1[idx]; sm.w1p[idx] = pack2(v, v); }
    if (tid < 192) { float v = w2[tid]; sm.w2p[tid] = pack2(v, v); }
    if (tid < 128) {   // zero pad cells of S: x = 0 and x = 57
        int n = tid >> 6, rem = tid & 63, h = rem >> 3, o = (rem >> 1) & 3;
        sm.S[n][h][o][(tid & 1) ? 57 : 0] = 0.f;
    }
    __syncthreads();

    // ---------------- Phase 1: pipelined compute ----------------
    const int kq  = tid / 112;
    const int rem = tid % 112;
    const int n   = rem / 56;
    const int hp  = (rem / 14) % 4;
    const int wq  = rem % 14;
    const int w0  = wq * 4;

    ull acc[2][4][2];
#pragma unroll
    for (int h = 0; h < 2; h++)
#pragma unroll
        for (int o = 0; o < 4; o++) { acc[h][o][0] = 0ull; acc[h][o][1] = 0ull; }

    for (int t = 0; t < 16; t++) {
        if (t < 15) asm volatile("cp.async.wait_group 1;" ::: "memory");
        else        asm volatile("cp.async.wait_group 0;" ::: "memory");
        __syncthreads();                 // tile t visible block-wide

        const float* xb = &sm.u.xtile[t & 1][kq][n][0][0];
        ulonglong2 v[4];
#pragma unroll
        for (int r = 0; r < 4; r++)
            v[r] = *reinterpret_cast<const ulonglong2*>(xb + (hp * 2 + r) * 60 + w0);

        const ulonglong2* wk = reinterpret_cast<const ulonglong2*>(&sm.w1p[(kq * 16 + t) * 12]);
#pragma unroll
        for (int p = 0; p < 6; p++) {
            ulonglong2 wv = wk[p];
            const int e0 = 2 * p,     i0 = e0 >> 2, o0 = e0 & 3;
            const int e1 = 2 * p + 1, i1 = e1 >> 2, o1 = e1 & 3;
            fma2(acc[0][o0][0], v[i0].x,     wv.x);
            fma2(acc[0][o0][1], v[i0].y,     wv.x);
            fma2(acc[1][o0][0], v[i0 + 1].x, wv.x);
            fma2(acc[1][o0][1], v[i0 + 1].y, wv.x);
            fma2(acc[0][o1][0], v[i1].x,     wv.y);
            fma2(acc[0][o1][1], v[i1].y,     wv.y);
            fma2(acc[1][o1][0], v[i1 + 1].x, wv.y);
            fma2(acc[1][o1][1], v[i1 + 1].y, wv.y);
        }

        __syncthreads();                 // all done reading buf (t&1)
        if (t + 2 < 16) issue(t + 2);    // refill it
    }

    // publish partials (xtile dead -> pbuf alias safe: trailing sync above)
    {
        ull* dst = &sm.u.pbuf[kq][rem][0];
#pragma unroll
        for (int h = 0; h < 2; h++)
#pragma unroll
            for (int o = 0; o < 4; o++)
#pragma unroll
                for (int wp = 0; wp < 2; wp++)
                    dst[(h * 4 + o) * 2 + wp] = acc[h][o][wp];
    }
    __syncthreads();

    // parallel reduction + t4 smem write: thread = (item, o)
    {
        const int it = tid % 112;
        const int o2 = tid / 112;
        ull s[2][2];
#pragma unroll
        for (int h = 0; h < 2; h++)
#pragma unroll
            for (int wp = 0; wp < 2; wp++)
                s[h][wp] = sm.u.pbuf[0][it][(h * 4 + o2) * 2 + wp];
#pragma unroll
        for (int q = 1; q < 4; q++)
#pragma unroll
            for (int h = 0; h < 2; h++)
#pragma unroll
                for (int wp = 0; wp < 2; wp++)
                    add2(s[h][wp], sm.u.pbuf[q][it][(h * 4 + o2) * 2 + wp]);

        const int rn  = it / 56;
        const int rhp = (it / 14) % 4;
        const int rw0 = (it % 14) * 4;
#pragma unroll
        for (int h = 0; h < 2; h++) {
            const int hr = rhp * 2 + h;
            *reinterpret_cast<ull*>(&sm.M[rn][hr][o2][rw0])     = s[h][0];
            *reinterpret_cast<ull*>(&sm.M[rn][hr][o2][rw0 + 2]) = s[h][1];
            sm.S[rn][hr][o2][rw0 + 1] = lo2(s[h][0]);
            *reinterpret_cast<ull*>(&sm.S[rn][hr][o2][rw0 + 2]) = pack2(hi2(s[h][0]), lo2(s[h][1]));
            sm.S[rn][hr][o2][rw0 + 4] = hi2(s[h][1]);
        }
    }
    __syncthreads();

    // ---------------- Phase 2 ----------------
    {
        const int tx = tid % 14;
        const int ty = tid / 14;
        const int o  = ty >> 3;
        const int j0 = (ty & 7) * 4;
        const int pw0 = tx * 4;

        for (int h = 0; h < CH; h++) {
            ull acc2[4][2];
#pragma unroll
            for (int jj = 0; jj < 4; jj++) { acc2[jj][0] = 0ull; acc2[jj][1] = 0ull; }

#pragma unroll
            for (int i = 0; i < 2; i++) {
#pragma unroll
                for (int kk = 0; kk < 3; kk++) {
                    ull p0, p1;
                    if (kk == 1) {
                        p0 = *reinterpret_cast<const ull*>(&sm.M[i][h][o][pw0]);
                        p1 = *reinterpret_cast<const ull*>(&sm.M[i][h][o][pw0 + 2]);
                    } else if (kk == 0) {
                        p0 = *reinterpret_cast<const ull*>(&sm.S[i][h][o][pw0]);
                        p1 = *reinterpret_cast<const ull*>(&sm.S[i][h][o][pw0 + 2]);
                    } else {
                        p0 = *reinterpret_cast<const ull*>(&sm.S[i][h][o][pw0 + 2]);
                        p1 = *reinterpret_cast<const ull*>(&sm.S[i][h][o][pw0 + 4]);
                    }
                    ulonglong2 Wa = *reinterpret_cast<const ulonglong2*>(&sm.w2p[i * 96 + kk * 32 + j0]);
                    ulonglong2 Wb = *reinterpret_cast<const ulonglong2*>(&sm.w2p[i * 96 + kk * 32 + j0 + 2]);
                    fma2(acc2[0][0], p0, Wa.x); fma2(acc2[0][1], p1, Wa.x);
                    fma2(acc2[1][0], p0, Wa.y); fma2(acc2[1][1], p1, Wa.y);
                    fma2(acc2[2][0], p0, Wb.x); fma2(acc2[2][1], p1, Wb.x);
                    fma2(acc2[3][0], p0, Wb.y); fma2(acc2[3][1], p1, Wb.y);
                }
            }

#pragma unroll
            for (int jj = 0; jj < 4; jj++) {
                int cc = (j0 + jj) * 4 + o;
                float4* p = reinterpret_cast<float4*>(
                    out + ((size_t)l * 128 + cc) * 3136 + (h0 + h) * 56 + pw0);
                *p = make_float4(lo2(acc2[jj][0]), hi2(acc2[jj][0]),
                                 lo2(acc2[jj][1]), hi2(acc2[jj][1]));
            }
        }
    }
}

extern "C" void kernel_launch(void* const* d_in, const int* in_sizes, int n_in,
                              void* d_out, int out_size)
{
    const float* x  = (const float*)d_in[0];
    const float* w1 = (const float*)d_in[1];
    const float* w2 = (const float*)d_in[2];
    float* out = (float*)d_out;

    cudaFuncSetAttribute(fused_kernel, cudaFuncAttributeMaxDynamicSharedMemorySize,
                         (int)SMEM_BYTES);
    fused_kernel<<<dim3(7, 128), 448, SMEM_BYTES>>>(x, w1, w2, out);
}

// round 7
// speedup vs baseline: 1.6013x; 1.0205x over previous
#include <cuda_runtime.h>
#include <cstdint>

typedef unsigned long long ull;

__device__ __forceinline__ ull pack2(float a, float b) {
    ull r; asm("mov.b64 %0,{%1,%2};" : "=l"(r) : "f"(a), "f"(b)); return r;
}
__device__ __forceinline__ void fma2(ull& d, ull a, ull b) {
    asm("fma.rn.f32x2 %0,%1,%2,%3;" : "=l"(d) : "l"(a), "l"(b), "l"(d));
}
__device__ __forceinline__ void add2(ull& d, ull a) {
    asm("add.rn.f32x2 %0,%1,%2;" : "=l"(d) : "l"(d), "l"(a));
}
__device__ __forceinline__ float lo2(ull a) { return __uint_as_float((unsigned)a); }
__device__ __forceinline__ float hi2(ull a) { return __uint_as_float((unsigned)(a >> 32)); }

#define CH 8                    // h rows per block (56 = 7 * 8)
#define NQUAD 1120              // 16B quads per tile: 4kq * 2n * 10rows * 14
#define XT_BYTES 19200          // bytes per x-tile buffer: 4*2*10*60*4

struct Smem {
    union {
        float xtile[3][4][2][10][60];   // [buf][kq][n][slot][w(pad 60)]
        ull   pbuf[4][112][17];         // partials, alias (xtile dead by then)
    } u;
    float M[2][CH][4][56];       // [n][h][o][w]  = t4 row
    float S[2][CH][4][60];       // [n][h][o][x]  = t4[x-1], 0 pad
    ull   w1p[768];              // [k][i][o] packed (w,w)
    ull   w2p[192];              // [i][kk][j] packed (w,w)
};
#define SMEM_BYTES sizeof(Smem)

// Fused kernel; phase 1 uses a TRIPLE-buffered cp.async pipeline with ONE
// barrier per k-tile: issue(t+2) writes the buffer last read at stage t-1,
// so the stage-t barrier both publishes tile t and frees buffer (t+2)%3.
__global__ __launch_bounds__(448, 2) void fused_kernel(
    const float* __restrict__ x, const float* __restrict__ w1,
    const float* __restrict__ w2, float* __restrict__ out)
{
    extern __shared__ __align__(16) char smraw[];
    Smem& sm = *reinterpret_cast<Smem*>(smraw);

    const int tid = threadIdx.x;
    const int h0  = blockIdx.x * CH;
    const int l   = blockIdx.y;

    // ---- per-thread cp.async quad descriptors (3 quads, last partial) ----
    const float* qsrc[3]; unsigned qdst[3]; int qsz[3];
#pragma unroll
    for (int i = 0; i < 3; i++) {
        int q  = tid + i * 448;          // i<2 always < NQUAD; i==2 iff tid<224
        int qq = (q < NQUAD) ? q : 0;
        int kq = qq / 280, n = (qq / 140) % 2, s = (qq / 14) % 10, wq = qq % 14;
        int hv  = h0 - 1 + s;            // virtual (rolled) tap row
        int inr = (hv >= 0 && hv < 56);
        int row = (hv == 0) ? 55 : hv - 1;
        qsrc[i] = x + ((size_t)l * 128 + 32 * kq + n) * 3136 + (inr ? row * 56 : 0) + wq * 4;
        qdst[i] = (unsigned)__cvta_generic_to_shared(&sm.u.xtile[0][kq][n][s][wq * 4]);
        qsz[i]  = inr ? 16 : 0;
    }

    auto issue = [&](int t) {
        unsigned bofs = (unsigned)((t % 3) * XT_BYTES);
        size_t   cofs = (size_t)(2 * t) * 3136;      // +2 channels per tile
#pragma unroll
        for (int i = 0; i < 3; i++) {
            if (i == 2 && tid >= 224) break;
            asm volatile("cp.async.cg.shared.global [%0], [%1], 16, %2;"
                         :: "r"(qdst[i] + bofs), "l"(qsrc[i] + cofs), "r"(qsz[i])
                         : "memory");
        }
        asm volatile("cp.async.commit_group;" ::: "memory");
    };

    issue(0); issue(1);                  // prologue: get DRAM going first

    for (int idx = tid; idx < 768; idx += 448) { float v = w1[idx]; sm.w1p[idx] = pack2(v, v); }
    if (tid < 192) { float v = w2[tid]; sm.w2p[tid] = pack2(v, v); }
    if (tid < 128) {   // zero pad cells of S: x = 0 and x = 57
        int n = tid >> 6, rem = tid & 63, h = rem >> 3, o = (rem >> 1) & 3;
        sm.S[n][h][o][(tid & 1) ? 57 : 0] = 0.f;
    }

    // ---------------- Phase 1: pipelined compute ----------------
    const int kq  = tid / 112;
    const int rem = tid % 112;
    const int n   = rem / 56;
    const int hp  = (rem / 14) % 4;
    const int wq  = rem % 14;
    const int w0  = wq * 4;

    ull acc[2][4][2];
#pragma unroll
    for (int h = 0; h < 2; h++)
#pragma unroll
        for (int o = 0; o < 4; o++) { acc[h][o][0] = 0ull; acc[h][o][1] = 0ull; }

    for (int t = 0; t < 16; t++) {
        if (t < 15) asm volatile("cp.async.wait_group 1;" ::: "memory");
        else        asm volatile("cp.async.wait_group 0;" ::: "memory");
        __syncthreads();                 // tile t visible; buf (t+2)%3 is free

        if (t + 2 < 16) issue(t + 2);    // overwrites buffer last read at t-1

        const float* xb = &sm.u.xtile[t % 3][kq][n][0][0];
        ulonglong2 v[4];
#pragma unroll
        for (int r = 0; r < 4; r++)
            v[r] = *reinterpret_cast<const ulonglong2*>(xb + (hp * 2 + r) * 60 + w0);

        const ulonglong2* wk = reinterpret_cast<const ulonglong2*>(&sm.w1p[(kq * 16 + t) * 12]);
#pragma unroll
        for (int p = 0; p < 6; p++) {
            ulonglong2 wv = wk[p];
            const int e0 = 2 * p,     i0 = e0 >> 2, o0 = e0 & 3;
            const int e1 = 2 * p + 1, i1 = e1 >> 2, o1 = e1 & 3;
            fma2(acc[0][o0][0], v[i0].x,     wv.x);
            fma2(acc[0][o0][1], v[i0].y,     wv.x);
            fma2(acc[1][o0][0], v[i0 + 1].x, wv.x);
            fma2(acc[1][o0][1], v[i0 + 1].y, wv.x);
            fma2(acc[0][o1][0], v[i1].x,     wv.y);
            fma2(acc[0][o1][1], v[i1].y,     wv.y);
            fma2(acc[1][o1][0], v[i1 + 1].x, wv.y);
            fma2(acc[1][o1][1], v[i1 + 1].y, wv.y);
        }
    }
    __syncthreads();                     // all reads of xtile done -> pbuf alias safe

    // publish partials
    {
        ull* dst = &sm.u.pbuf[kq][rem][0];
#pragma unroll
        for (int h = 0; h < 2; h++)
#pragma unroll
            for (int o = 0; o < 4; o++)
#pragma unroll
                for (int wp = 0; wp < 2; wp++)
                    dst[(h * 4 + o) * 2 + wp] = acc[h][o][wp];
    }
    __syncthreads();

    // parallel reduction + t4 smem write: thread = (item, o)
    {
        const int it = tid % 112;
        const int o2 = tid / 112;
        ull s[2][2];
#pragma unroll
        for (int h = 0; h < 2; h++)
#pragma unroll
            for (int wp = 0; wp < 2; wp++)
                s[h][wp] = sm.u.pbuf[0][it][(h * 4 + o2) * 2 + wp];
#pragma unroll
        for (int q = 1; q < 4; q++)
#pragma unroll
            for (int h = 0; h < 2; h++)
#pragma unroll
                for (int wp = 0; wp < 2; wp++)
                    add2(s[h][wp], sm.u.pbuf[q][it][(h * 4 + o2) * 2 + wp]);

        const int rn  = it / 56;
        const int rhp = (it / 14) % 4;
        const int rw0 = (it % 14) * 4;
#pragma unroll
        for (int h = 0; h < 2; h++) {
            const int hr = rhp * 2 + h;
            *reinterpret_cast<ull*>(&sm.M[rn][hr][o2][rw0])     = s[h][0];
            *reinterpret_cast<ull*>(&sm.M[rn][hr][o2][rw0 + 2]) = s[h][1];
            sm.S[rn][hr][o2][rw0 + 1] = lo2(s[h][0]);
            *reinterpret_cast<ull*>(&sm.S[rn][hr][o2][rw0 + 2]) = pack2(hi2(s[h][0]), lo2(s[h][1]));
            sm.S[rn][hr][o2][rw0 + 4] = hi2(s[h][1]);
        }
    }
    __syncthreads();

    // ---------------- Phase 2 ----------------
    {
        const int tx = tid % 14;
        const int ty = tid / 14;
        const int o  = ty >> 3;
        const int j0 = (ty & 7) * 4;
        const int pw0 = tx * 4;

        for (int h = 0; h < CH; h++) {
            ull acc2[4][2];
#pragma unroll
            for (int jj = 0; jj < 4; jj++) { acc2[jj][0] = 0ull; acc2[jj][1] = 0ull; }

#pragma unroll
            for (int i = 0; i < 2; i++) {
#pragma unroll
                for (int kk = 0; kk < 3; kk++) {
                    ull p0, p1;
                    if (kk == 1) {
                        p0 = *reinterpret_cast<const ull*>(&sm.M[i][h][o][pw0]);
                        p1 = *reinterpret_cast<const ull*>(&sm.M[i][h][o][pw0 + 2]);
                    } else if (kk == 0) {
                        p0 = *reinterpret_cast<const ull*>(&sm.S[i][h][o][pw0]);
                        p1 = *reinterpret_cast<const ull*>(&sm.S[i][h][o][pw0 + 2]);
                    } else {
                        p0 = *reinterpret_cast<const ull*>(&sm.S[i][h][o][pw0 + 2]);
                        p1 = *reinterpret_cast<const ull*>(&sm.S[i][h][o][pw0 + 4]);
                    }
                    ulonglong2 Wa = *reinterpret_cast<const ulonglong2*>(&sm.w2p[i * 96 + kk * 32 + j0]);
                    ulonglong2 Wb = *reinterpret_cast<const ulonglong2*>(&sm.w2p[i * 96 + kk * 32 + j0 + 2]);
                    fma2(acc2[0][0], p0, Wa.x); fma2(acc2[0][1], p1, Wa.x);
                    fma2(acc2[1][0], p0, Wa.y); fma2(acc2[1][1], p1, Wa.y);
                    fma2(acc2[2][0], p0, Wb.x); fma2(acc2[2][1], p1, Wb.x);
                    fma2(acc2[3][0], p0, Wb.y); fma2(acc2[3][1], p1, Wb.y);
                }
            }

#pragma unroll
            for (int jj = 0; jj < 4; jj++) {
                int cc = (j0 + jj) * 4 + o;
                float4* p = reinterpret_cast<float4*>(
                    out + ((size_t)l * 128 + cc) * 3136 + (h0 + h) * 56 + pw0);
                *p = make_float4(lo2(acc2[jj][0]), hi2(acc2[jj][0]),
                                 lo2(acc2[jj][1]), hi2(acc2[jj][1]));
            }
        }
    }
}

extern "C" void kernel_launch(void* const* d_in, const int* in_sizes, int n_in,
                              void* d_out, int out_size)
{
    const float* x  = (const float*)d_in[0];
    const float* w1 = (const float*)d_in[1];
    const float* w2 = (const float*)d_in[2];
    float* out = (float*)d_out;

    cudaFuncSetAttribute(fused_kernel, cudaFuncAttributeMaxDynamicSharedMemorySize,
                         (int)SMEM_BYTES);
    fused_kernel<<<dim3(7, 128), 448, SMEM_BYTES>>>(x, w1, w2, out);
}